// round 2
// baseline (speedup 1.0000x reference)
#include <cuda_runtime.h>

#define NTHREADS 128

// inverse of the low-5-bit source-permutation pi0 (see derivation in analysis)
__device__ constexpr int pi0inv(int m) {
    int m0 = m & 1, m1 = (m >> 1) & 1, m2 = (m >> 2) & 1, m3 = (m >> 3) & 1, m4 = (m >> 4) & 1;
    int r0 = m0 ^ m1;
    int r1 = m1 ^ m2 ^ m3;
    int r2 = m2 ^ m3;
    int r3 = m3 ^ m4;
    int r4 = m4;
    return r0 | (r1 << 1) | (r2 << 2) | (r3 << 3) | (r4 << 4);
}

// RY butterfly over register-index bit K: new0 = c*x0 - s*x1 ; new1 = s*x0 + c*x1
template <int K>
__device__ __forceinline__ void ry_stage(float* a, float c, float s) {
#pragma unroll
    for (int r = 0; r < 32; ++r) {
        if ((r & (1 << K)) == 0) {
            float x0 = a[r];
            float x1 = a[r | (1 << K)];
            a[r]            = fmaf(c, x0, -(s * x1));
            a[r | (1 << K)] = fmaf(s, x0, c * x1);
        }
    }
}

__global__ void __launch_bounds__(NTHREADS)
qsim_kernel(const float* __restrict__ feats,
            const float* __restrict__ qp,
            float* __restrict__ out)
{
    // state, stored XOR-swizzled: phys_elem = idx ^ (((idx>>5)&7)<<2)
    __shared__ float4 st4[1024];
    float* stf = reinterpret_cast<float*>(st4);
    __shared__ float csc[240], css[240];
    __shared__ float warp_ssq[4];
    __shared__ float rsum[48];
    __shared__ float inv_total;

    const int t = threadIdx.x;
    const int b = blockIdx.x;

    // ---- per-layer RY coefficients: theta = qp[(L+1)*12 + j], c=cos(th/2), s=sin(th/2)
    for (int i = t; i < 240; i += NTHREADS) {
        float th = 0.5f * qp[12 + i];
        csc[i] = cosf(th);
        css[i] = sinf(th);
    }

    // ---- embed: tanh(x)*pi/2 for 2048 feats, 0.5 padding for the rest (unnormalized;
    //      the 1/||s||^2 factor is applied to the final expvals since everything is linear)
    const float4* frow = reinterpret_cast<const float4*>(feats + (size_t)b * 2048);
    const float PIO2 = 1.5707963267948966f;
    float acc = 4.0f;  // this thread's share of the padding sum-sq: 16 * 0.25
#pragma unroll
    for (int v = 0; v < 4; ++v) {
        int f4i = v * 128 + t;
        float4 x = frow[f4i];
        float4 y;
        y.x = tanhf(x.x) * PIO2;
        y.y = tanhf(x.y) * PIO2;
        y.z = tanhf(x.z) * PIO2;
        y.w = tanhf(x.w) * PIO2;
        acc += y.x * y.x + y.y * y.y + y.z * y.z + y.w * y.w;
        st4[f4i ^ ((f4i >> 3) & 7)] = y;
    }
#pragma unroll
    for (int v = 0; v < 4; ++v) {
        int f4i = 512 + v * 128 + t;
        st4[f4i ^ ((f4i >> 3) & 7)] = make_float4(0.5f, 0.5f, 0.5f, 0.5f);
    }

    // block reduce sum of squares
#pragma unroll
    for (int o = 16; o; o >>= 1) acc += __shfl_xor_sync(0xffffffffu, acc, o);
    if ((t & 31) == 0) warp_ssq[t >> 5] = acc;
    __syncthreads();
    if (t == 0)
        inv_total = 1.0f / (warp_ssq[0] + warp_ssq[1] + warp_ssq[2] + warp_ssq[3]);

    // ---- pass-A thread constants: source thread-block sigma(t) for the entangling gather
    int t0 = t & 1, t1 = (t >> 1) & 1, t2 = (t >> 2) & 1, t3 = (t >> 3) & 1;
    int t4 = (t >> 4) & 1, t5 = (t >> 5) & 1, t6 = (t >> 6) & 1;
    int hi = (t0 ^ t1)
           | ((t1 ^ t2 ^ t3) << 1)
           | ((t2 ^ t3) << 2)
           | ((t3 ^ t4 ^ t5) << 3)
           | ((t4 ^ t5) << 4)
           | ((t5 ^ t6) << 5)
           | (t6 << 6);
    int e   = t0 ^ t1;               // parity feeding src bit 4
    int xA  = (e << 2) ^ (hi & 7);   // float4-granularity XOR: load perm + bank swizzle
    int hi8 = hi * 8;
    int baseB = ((t >> 5) << 10) | (t & 31);
    int xC = (t >> 2) & 7;
    __syncthreads();

#pragma unroll 1
    for (int L = 0; L < 20; ++L) {
        const float* cc = &csc[L * 12];
        const float* ss = &css[L * 12];

        // ===== pass A: entangling gather + RY on qubits 11..7 (idx bits 0..4) =====
        float rg[32];
#pragma unroll
        for (int j = 0; j < 8; ++j) {
            float4 v = st4[hi8 + (j ^ xA)];
            rg[pi0inv(4 * j + 0)] = v.x;
            rg[pi0inv(4 * j + 1)] = v.y;
            rg[pi0inv(4 * j + 2)] = v.z;
            rg[pi0inv(4 * j + 3)] = v.w;
        }
        ry_stage<0>(rg, cc[11], ss[11]);
        ry_stage<1>(rg, cc[10], ss[10]);
        ry_stage<2>(rg, cc[9], ss[9]);
        ry_stage<3>(rg, cc[8], ss[8]);
        ry_stage<4>(rg, cc[7], ss[7]);
        __syncthreads();  // all gathers done before overwriting blocks
#pragma unroll
        for (int j = 0; j < 8; ++j)
            st4[t * 8 + (j ^ (t & 7))] =
                make_float4(rg[4 * j], rg[4 * j + 1], rg[4 * j + 2], rg[4 * j + 3]);
        __syncthreads();

        // ===== pass B: RY on qubits 6..2 (idx bits 5..9), in-place per-thread set =====
        float bm[32];
#pragma unroll
        for (int m = 0; m < 32; ++m)
            bm[m] = stf[baseB ^ ((m << 5) ^ ((m & 7) << 2))];
        ry_stage<0>(bm, cc[6], ss[6]);
        ry_stage<1>(bm, cc[5], ss[5]);
        ry_stage<2>(bm, cc[4], ss[4]);
        ry_stage<3>(bm, cc[3], ss[3]);
        ry_stage<4>(bm, cc[2], ss[2]);
#pragma unroll
        for (int m = 0; m < 32; ++m)
            stf[baseB ^ ((m << 5) ^ ((m & 7) << 2))] = bm[m];
        __syncthreads();

        // ===== pass C: RY on qubits 1,0 (idx bits 10,11), in-place per-thread set =====
        float cv[32];
#pragma unroll
        for (int g = 0; g < 4; ++g)
#pragma unroll
            for (int hb = 0; hb < 2; ++hb) {
                float4 v = st4[(((g << 8) | (t << 1) | hb)) ^ xC];
                int rb = g * 8 + hb * 4;
                cv[rb + 0] = v.x; cv[rb + 1] = v.y; cv[rb + 2] = v.z; cv[rb + 3] = v.w;
            }
        ry_stage<4>(cv, cc[0], ss[0]);  // r bit4 = idx bit11 = qubit 0
        ry_stage<3>(cv, cc[1], ss[1]);  // r bit3 = idx bit10 = qubit 1
#pragma unroll
        for (int g = 0; g < 4; ++g)
#pragma unroll
            for (int hb = 0; hb < 2; ++hb) {
                int rb = g * 8 + hb * 4;
                st4[(((g << 8) | (t << 1) | hb)) ^ xC] =
                    make_float4(cv[rb], cv[rb + 1], cv[rb + 2], cv[rb + 3]);
            }
        __syncthreads();
    }

    // ===== expvals: out[q] = inv * sum_i s_i^2 * (1 - 2*bit_{11-q}(i)) =====
    float S = 0.f;
    float T[5] = {0.f, 0.f, 0.f, 0.f, 0.f};
#pragma unroll
    for (int j = 0; j < 8; ++j) {
        float4 v = st4[t * 8 + (j ^ (t & 7))];
        float vv[4] = {v.x, v.y, v.z, v.w};
#pragma unroll
        for (int k = 0; k < 4; ++k) {
            int r = 4 * j + k;
            float pp = vv[k] * vv[k];
            S += pp;
            if (r & 1)  T[0] += pp;
            if (r & 2)  T[1] += pp;
            if (r & 4)  T[2] += pp;
            if (r & 8)  T[3] += pp;
            if (r & 16) T[4] += pp;
        }
    }
    float val[12];
#pragma unroll
    for (int q = 0; q <= 6; ++q)
        val[q] = ((t >> (6 - q)) & 1) ? -S : S;   // idx bit (11-q) lives in thread bits
#pragma unroll
    for (int q = 7; q < 12; ++q)
        val[q] = S - 2.0f * T[11 - q];            // idx bit (11-q) lives in register bits

#pragma unroll
    for (int q = 0; q < 12; ++q)
#pragma unroll
        for (int o = 16; o; o >>= 1)
            val[q] += __shfl_xor_sync(0xffffffffu, val[q], o);
    if ((t & 31) == 0) {
#pragma unroll
        for (int q = 0; q < 12; ++q) rsum[(t >> 5) * 12 + q] = val[q];
    }
    __syncthreads();
    if (t < 12) {
        out[(size_t)b * 12 + t] =
            (rsum[t] + rsum[12 + t] + rsum[24 + t] + rsum[36 + t]) * inv_total;
    }
}

extern "C" void kernel_launch(void* const* d_in, const int* in_sizes, int n_in,
                              void* d_out, int out_size) {
    const float* feats = (const float*)d_in[0];
    const float* qp    = (const float*)d_in[1];
    float* out         = (float*)d_out;
    qsim_kernel<<<4096, NTHREADS>>>(feats, qp, out);
}

// round 3
// speedup vs baseline: 1.6630x; 1.6630x over previous
#include <cuda_runtime.h>

#define NT 128

// inverse of the 6-bit source-permutation pi0 (entangling layer, idx bits 0..5)
// pi0: n0=m0^m1^m2, n1=m1^m2, n2=m2^m3^m4, n3=m3^m4, n4=m4^m5, n5=m5
__device__ constexpr int pi0inv6(int n) {
    int n0 = n & 1, n1 = (n >> 1) & 1, n2 = (n >> 2) & 1;
    int n3 = (n >> 3) & 1, n4 = (n >> 4) & 1, n5 = (n >> 5) & 1;
    int m0 = n0 ^ n1;
    int m1 = n1 ^ n2 ^ n3;
    int m2 = n2 ^ n3;
    int m3 = n3 ^ n4 ^ n5;
    int m4 = n4 ^ n5;
    int m5 = n5;
    return m0 | (m1 << 1) | (m2 << 2) | (m3 << 3) | (m4 << 4) | (m5 << 5);
}

// tan-form RY butterfly over register-index bit K (2 FFMA per pair; the
// cos scale is folded into the global output scale G^2)
template <int K>
__device__ __forceinline__ void stage(float* a, float tc) {
#pragma unroll
    for (int r = 0; r < 64; ++r) {
        if ((r & (1 << K)) == 0) {
            float x0 = a[r];
            float x1 = a[r | (1 << K)];
            a[r]            = fmaf(-tc, x1, x0);
            a[r | (1 << K)] = fmaf( tc, x0, x1);
        }
    }
}

__global__ void __launch_bounds__(NT)
qsim_kernel(const float* __restrict__ feats,
            const float* __restrict__ qp,
            float* __restrict__ out)
{
    // two rows per CTA; swizzle: phys4 = f4 ^ ((f4>>4)&7)  (f4 = idx>>2)
    __shared__ float4 st4[2048];
    float* stf = reinterpret_cast<float*>(st4);
    __shared__ float tt[240];
    __shared__ float wred[4];     // per-warp ssq partials
    __shared__ float gred[4];     // per-warp cos-product partials
    __shared__ float oscale[2];   // G^2 / ||embed||^2 per row
    __shared__ float rsum[4][12];

    const int t    = threadIdx.x;
    const int row  = t >> 6;
    const int u    = t & 63;
    const int lane = t & 31;
    const int b    = blockIdx.x;

    // ---- tan table + global cos product G
    float gpart = 1.0f;
    for (int i = t; i < 240; i += NT) {
        float th = 0.5f * qp[12 + i];
        float s, c;
        sincosf(th, &s, &c);
        tt[i] = s / c;
        gpart *= c;
    }
#pragma unroll
    for (int o = 16; o; o >>= 1) gpart *= __shfl_xor_sync(0xffffffffu, gpart, o);
    if (lane == 0) gred[t >> 5] = gpart;

    // ---- embedding: tanh(x)*pi/2 (2048 feats) + 0.5 padding, unnormalized
    const float4* frow = reinterpret_cast<const float4*>(feats + (size_t)(b * 2 + row) * 2048);
    const float PIO2 = 1.5707963267948966f;
    const int rb4 = row << 10;   // float4 base of this row
    float acc = 8.0f;            // this thread's padding ssq share: 32 * 0.25
#pragma unroll
    for (int v = 0; v < 8; ++v) {
        int f4i = v * 64 + u;
        float4 x = frow[f4i];
        float4 y;
        y.x = tanhf(x.x) * PIO2;
        y.y = tanhf(x.y) * PIO2;
        y.z = tanhf(x.z) * PIO2;
        y.w = tanhf(x.w) * PIO2;
        acc += y.x * y.x + y.y * y.y + y.z * y.z + y.w * y.w;
        st4[rb4 + (f4i ^ ((f4i >> 4) & 7))] = y;
    }
#pragma unroll
    for (int v = 8; v < 16; ++v) {
        int f4i = v * 64 + u;
        st4[rb4 + (f4i ^ ((f4i >> 4) & 7))] = make_float4(0.5f, 0.5f, 0.5f, 0.5f);
    }
#pragma unroll
    for (int o = 16; o; o >>= 1) acc += __shfl_xor_sync(0xffffffffu, acc, o);
    if (lane == 0) wred[t >> 5] = acc;
    __syncthreads();
    if (t < 2) {
        float G = gred[0] * gred[1] * gred[2] * gred[3];
        oscale[t] = (G * G) / (wred[2 * t] + wred[2 * t + 1]);
    }

    // ---- per-thread constants
    // pass-1 source thread-block: src idx bits 6..11 as function of u bits
    int u0 = u & 1, u1 = (u >> 1) & 1, u2 = (u >> 2) & 1;
    int u3 = (u >> 3) & 1, u4 = (u >> 4) & 1, u5 = (u >> 5) & 1;
    int Hs = (u0 ^ u1 ^ u2)
           | ((u1 ^ u2) << 1)
           | ((u2 ^ u3 ^ u4) << 2)
           | ((u3 ^ u4) << 3)
           | ((u4 ^ u5) << 4)
           | (u5 << 5);
    int K1  = (u0 ? 0xC : 0) ^ (Hs & 7);  // gather XOR: parity term + bank swizzle
    int lb4 = rb4 + Hs * 16;              // pass-1 load base (float4)
    int sb4 = rb4 + u * 16;               // pass-1 store base (float4)
    int xs  = u & 7;                      // pass-1 store swizzle
    // pass-2 scalar bases (float units): elem (m<<6)|u at p2b[m&7] + m*64
    const int rowf = row << 12;
    int p2b[8];
#pragma unroll
    for (int k = 0; k < 8; ++k)
        p2b[k] = rowf + ((((u >> 2) ^ k) << 2) | (u & 3));

#pragma unroll 1
    for (int L = 0; L < 20; ++L) {
        const float* tc = &tt[L * 12];

        // ===== pass 1: entangling gather + RY qubits 11..6 (idx bits 0..5) =====
        float rg[64];
#pragma unroll
        for (int pp = 0; pp < 16; ++pp) {
            float4 v = st4[lb4 + (pp ^ K1)];
            rg[pi0inv6(pp * 4 + 0)] = v.x;
            rg[pi0inv6(pp * 4 + 1)] = v.y;
            rg[pi0inv6(pp * 4 + 2)] = v.z;
            rg[pi0inv6(pp * 4 + 3)] = v.w;
        }
        stage<0>(rg, tc[11]);
        stage<1>(rg, tc[10]);
        stage<2>(rg, tc[9]);
        stage<3>(rg, tc[8]);
        stage<4>(rg, tc[7]);
        stage<5>(rg, tc[6]);
        __syncthreads();   // all gathers complete before blocks are overwritten
#pragma unroll
        for (int j = 0; j < 16; ++j)
            st4[sb4 + (j ^ xs)] =
                make_float4(rg[4 * j], rg[4 * j + 1], rg[4 * j + 2], rg[4 * j + 3]);
        __syncthreads();

        // ===== pass 2: RY qubits 5..0 (idx bits 6..11), thread-disjoint in-place =====
        float bm[64];
#pragma unroll
        for (int m = 0; m < 64; ++m)
            bm[m] = stf[p2b[m & 7] + m * 64];
        stage<0>(bm, tc[5]);
        stage<1>(bm, tc[4]);
        stage<2>(bm, tc[3]);
        stage<3>(bm, tc[2]);
        stage<4>(bm, tc[1]);
        stage<5>(bm, tc[0]);

        if (L < 19) {
#pragma unroll
            for (int m = 0; m < 64; ++m)
                stf[p2b[m & 7] + m * 64] = bm[m];
            __syncthreads();
        } else {
            // ===== expvals straight from registers (skip final store) =====
            // element idx = (m<<6) | u ; qubit q reads idx bit (11-q)
            float S = 0.f, T0 = 0.f, T1 = 0.f, T2 = 0.f, T3 = 0.f, T4 = 0.f, T5 = 0.f;
#pragma unroll
            for (int m = 0; m < 64; ++m) {
                float p = bm[m] * bm[m];
                S += p;
                if (m & 1)  T0 += p;
                if (m & 2)  T1 += p;
                if (m & 4)  T2 += p;
                if (m & 8)  T3 += p;
                if (m & 16) T4 += p;
                if (m & 32) T5 += p;
            }
            float val[12];
            val[0] = S - 2.f * T5;   // q=0 -> idx bit 11 -> m bit 5
            val[1] = S - 2.f * T4;
            val[2] = S - 2.f * T3;
            val[3] = S - 2.f * T2;
            val[4] = S - 2.f * T1;
            val[5] = S - 2.f * T0;   // q=5 -> idx bit 6 -> m bit 0
#pragma unroll
            for (int q = 6; q < 12; ++q)
                val[q] = ((u >> (11 - q)) & 1) ? -S : S;   // thread bits
#pragma unroll
            for (int q = 0; q < 12; ++q) {
#pragma unroll
                for (int o = 16; o; o >>= 1)
                    val[q] += __shfl_xor_sync(0xffffffffu, val[q], o);
            }
            if (lane == 0) {
#pragma unroll
                for (int q = 0; q < 12; ++q) rsum[t >> 5][q] = val[q];
            }
        }
    }

    __syncthreads();
    if (t < 24) {
        int r = t / 12, q = t % 12;
        out[(size_t)(b * 2 + r) * 12 + q] =
            (rsum[2 * r][q] + rsum[2 * r + 1][q]) * oscale[r];
    }
}

extern "C" void kernel_launch(void* const* d_in, const int* in_sizes, int n_in,
                              void* d_out, int out_size) {
    const float* feats = (const float*)d_in[0];
    const float* qp    = (const float*)d_in[1];
    float* out         = (float*)d_out;
    qsim_kernel<<<2048, NT>>>(feats, qp, out);
}

// round 4
// speedup vs baseline: 1.7562x; 1.0560x over previous
#include <cuda_runtime.h>

#define NT 128
typedef unsigned long long u64;

__device__ __forceinline__ u64 pk2(float x, float y) {
    u64 r; asm("mov.b64 %0,{%1,%2};" : "=l"(r) : "f"(x), "f"(y)); return r;
}
__device__ __forceinline__ void upk2(u64 v, float& x, float& y) {
    asm("mov.b64 {%0,%1},%2;" : "=f"(x), "=f"(y) : "l"(v));
}
__device__ __forceinline__ u64 ffma2(u64 a, u64 b, u64 c) {
    u64 d; asm("fma.rn.f32x2 %0,%1,%2,%3;" : "=l"(d) : "l"(a), "l"(b), "l"(c)); return d;
}

// packed butterfly over pair-index bit B (both lanes of the f32x2 move together)
template <int B>
__device__ __forceinline__ void vstage(u64* v, float t) {
    u64 tp = pk2(t, t), tn = pk2(-t, -t);
#pragma unroll
    for (int a = 0; a < 32; ++a)
        if (!(a & (1 << B))) {
            u64 A = v[a], Bv = v[a | (1 << B)];
            v[a]            = ffma2(tn, Bv, A);   // A - t*B
            v[a | (1 << B)] = ffma2(tp, A, Bv);   // t*A + B
        }
}

// src L-bits (idx bits 1..5, pre-parity) of the entangling gather for dst pair j
__device__ constexpr int QL(int j) {
    int j0 = j & 1, j1 = (j >> 1) & 1, j2 = (j >> 2) & 1, j3 = (j >> 3) & 1, j4 = (j >> 4) & 1;
    return (j0 ^ j1) | ((j1 ^ j2 ^ j3) << 1) | ((j2 ^ j3) << 2) | ((j3 ^ j4) << 3) | (j4 << 4);
}

__global__ void __launch_bounds__(NT)
qsim_kernel(const float* __restrict__ feats,
            const float* __restrict__ qp,
            float* __restrict__ out)
{
    // layout: addrF(idx) = H*64 + ((L5 ^ (H&31))<<1 | d0); H=idx>>6, L5=(idx>>1)&31, d0=idx&1
    __shared__ float2 st2s[4096];   // 2 rows x 2048 float2
    float* stf = reinterpret_cast<float*>(st2s);
    __shared__ float tt[240];
    __shared__ float wred[4], gred[4], oscale[2];
    __shared__ float rsum[4][12];

    const int t    = threadIdx.x;
    const int row  = t >> 6;
    const int u    = t & 63;
    const int lane = t & 31;
    const int b    = blockIdx.x;

    // tan table + global cos product (cos factors folded into output scale G^2)
    float gpart = 1.0f;
    for (int i = t; i < 240; i += NT) {
        float s, c; sincosf(0.5f * qp[12 + i], &s, &c);
        tt[i] = s / c; gpart *= c;
    }
#pragma unroll
    for (int o = 16; o; o >>= 1) gpart *= __shfl_xor_sync(~0u, gpart, o);
    if (lane == 0) gred[t >> 5] = gpart;

    // embedding (unnormalized; 1/||s||^2 folded into output scale)
    const float2* f2 = reinterpret_cast<const float2*>(feats + (size_t)(b * 2 + row) * 2048);
    float2* row2 = st2s + (row << 11);
    const float PIO2 = 1.5707963267948966f;
    float acc = 8.0f;  // padding ssq share: 32 * 0.25
#pragma unroll
    for (int v = 0; v < 16; ++v) {
        int p = v * 64 + u;
        float2 x = f2[p];
        float2 y = make_float2(tanhf(x.x) * PIO2, tanhf(x.y) * PIO2);
        acc += y.x * y.x + y.y * y.y;
        int h5 = p >> 5;
        row2[h5 * 32 + ((p & 31) ^ (h5 & 31))] = y;
    }
#pragma unroll
    for (int v = 16; v < 32; ++v) {
        int p = v * 64 + u;
        int h5 = p >> 5;
        row2[h5 * 32 + ((p & 31) ^ (h5 & 31))] = make_float2(0.5f, 0.5f);
    }
#pragma unroll
    for (int o = 16; o; o >>= 1) acc += __shfl_xor_sync(~0u, acc, o);
    if (lane == 0) wred[t >> 5] = acc;
    __syncthreads();
    if (t < 2) {
        float G = gred[0] * gred[1] * gred[2] * gred[3];
        oscale[t] = (G * G) / (wred[2 * t] + wred[2 * t + 1]);
    }

    // per-thread constants
    int u0 = u & 1, u1 = (u >> 1) & 1, u2b = (u >> 2) & 1;
    int u3 = (u >> 3) & 1, u4 = (u >> 4) & 1, u5 = (u >> 5) & 1;
    int Hs = (u0 ^ u1 ^ u2b)
           | ((u1 ^ u2b) << 1)
           | ((u2b ^ u3 ^ u4) << 2)
           | ((u3 ^ u4) << 3)
           | ((u4 ^ u5) << 4)
           | (u5 << 5);
    int xm = (u0 ? 0x18 : 0) ^ (Hs & 31);   // parity term (src bits 4,5) + swizzle
    float2* gbase = row2 + Hs * 32;          // pass-1 gather base
    float2* sbase = row2 + u * 32;           // pass-1 store base
    int sm = u & 31;
    float* rowf = stf + (row << 12);

#pragma unroll 1
    for (int L = 0; L < 20; ++L) {
        const float* tc = &tt[L * 12];

        // ===== pass 1: entangling gather + RY qubits 11..6 (idx bits 0..5) =====
        u64 vr[32];
        float t11 = tc[11];
#pragma unroll
        for (int j = 0; j < 32; ++j) {
            float2 w = gbase[QL(j) ^ xm];
            float x0, x1;  // x0 = src of dst(d0=0); mem .x holds q0=0 <=> r0 = j0^j1
            if (((j ^ (j >> 1)) & 1) == 0) { x0 = w.x; x1 = w.y; }
            else                            { x0 = w.y; x1 = w.x; }
            // fold qubit-11 stage (d0) into the load
            vr[j] = pk2(fmaf(-t11, x1, x0), fmaf(t11, x0, x1));
        }
        vstage<0>(vr, tc[10]);
        vstage<1>(vr, tc[9]);
        vstage<2>(vr, tc[8]);
        vstage<3>(vr, tc[7]);
        vstage<4>(vr, tc[6]);
        __syncthreads();   // all gathers complete before in-place overwrite
#pragma unroll
        for (int j = 0; j < 32; ++j) {
            float x, y; upk2(vr[j], x, y);
            sbase[j ^ sm] = make_float2(x, y);
        }
        __syncthreads();

        // ===== pass 2: RY qubits 5..0 (idx bits 6..11), in-place =====
        u64 vp[32];
        float t5 = tc[5];
#pragma unroll
        for (int a = 0; a < 32; ++a) {
            float x0 = rowf[(2 * a) * 64     + (u ^ ((4 * a)     & 62))];
            float x1 = rowf[(2 * a + 1) * 64 + (u ^ ((4 * a + 2) & 62))];
            // fold qubit-5 stage (idx bit 6) into the load
            vp[a] = pk2(fmaf(-t5, x1, x0), fmaf(t5, x0, x1));
        }
        vstage<0>(vp, tc[4]);
        vstage<1>(vp, tc[3]);
        vstage<2>(vp, tc[2]);
        vstage<3>(vp, tc[1]);
        vstage<4>(vp, tc[0]);

        if (L < 19) {
#pragma unroll
            for (int a = 0; a < 32; ++a) {
                float x, y; upk2(vp[a], x, y);
                rowf[(2 * a) * 64     + (u ^ ((4 * a)     & 62))] = x;
                rowf[(2 * a + 1) * 64 + (u ^ ((4 * a + 2) & 62))] = y;
            }
            __syncthreads();
        } else {
            // ===== expvals straight from registers =====
            // component (.x/.y) = idx bit 6 (qubit 5); a bits 0..4 = idx bits 7..11 (qubits 4..0)
            float S = 0.f, Ty = 0.f, T0 = 0.f, T1 = 0.f, T2 = 0.f, T3 = 0.f, T4 = 0.f;
#pragma unroll
            for (int a = 0; a < 32; ++a) {
                float x, y; upk2(vp[a], x, y);
                float px = x * x, py = y * y, ps = px + py;
                S += ps; Ty += py;
                if (a & 1)  T0 += ps;
                if (a & 2)  T1 += ps;
                if (a & 4)  T2 += ps;
                if (a & 8)  T3 += ps;
                if (a & 16) T4 += ps;
            }
            float val[12];
            val[0] = S - 2.f * T4;   // qubit 0 = idx bit 11 = a bit 4
            val[1] = S - 2.f * T3;
            val[2] = S - 2.f * T2;
            val[3] = S - 2.f * T1;
            val[4] = S - 2.f * T0;
            val[5] = S - 2.f * Ty;   // qubit 5 = idx bit 6 = component
#pragma unroll
            for (int q = 6; q < 12; ++q)
                val[q] = ((u >> (11 - q)) & 1) ? -S : S;   // thread bits
#pragma unroll
            for (int q = 0; q < 12; ++q) {
#pragma unroll
                for (int o = 16; o; o >>= 1)
                    val[q] += __shfl_xor_sync(~0u, val[q], o);
            }
            if (lane == 0) {
#pragma unroll
                for (int q = 0; q < 12; ++q) rsum[t >> 5][q] = val[q];
            }
        }
    }

    __syncthreads();
    if (t < 24) {
        int r = t / 12, q = t % 12;
        out[(size_t)(b * 2 + r) * 12 + q] =
            (rsum[2 * r][q] + rsum[2 * r + 1][q]) * oscale[r];
    }
}

extern "C" void kernel_launch(void* const* d_in, const int* in_sizes, int n_in,
                              void* d_out, int out_size) {
    const float* feats = (const float*)d_in[0];
    const float* qp    = (const float*)d_in[1];
    float* out         = (float*)d_out;
    qsim_kernel<<<2048, NT>>>(feats, qp, out);
}